// round 1
// baseline (speedup 1.0000x reference)
#include <cuda_runtime.h>

#define MAXROWS 32768
#define MAXPART 8192
#define BLK 256

__device__ float g_mask[MAXROWS];   // 1.0 if row valid else 0.0
__device__ float g_corr[MAXROWS];   // masked ((l1p_t - lp_t)/W + (l1p_t - lp_t)/H)
__device__ float g_part[MAXPART];   // per-block partials of -invL * sum(mask * l1p)

__device__ __forceinline__ float clog1m(float p) {
    // clamp(log(1-p), -100)  (torch BCELoss style clamp)
    return fmaxf(__logf(1.0f - p), -100.0f);
}

// ---------------------------------------------------------------------------
// Setup: per-row mask + gathered target-index correction terms
// ---------------------------------------------------------------------------
__global__ void setup_kernel(const float* __restrict__ px, const float* __restrict__ py,
                             const long long* __restrict__ tgt,
                             int rows, int W, int H, float invW, float invH)
{
    int r = blockIdx.x * blockDim.x + threadIdx.x;
    if (r >= rows) return;
    long long t0 = tgt[2 * r + 0];
    long long t1 = tgt[2 * r + 1];
    int tx = (int)t0; tx = tx < 0 ? 0 : (tx > W - 1 ? W - 1 : tx);
    int ty = (int)t1; ty = ty < 0 ? 0 : (ty > H - 1 ? H - 1 : ty);
    float m = (tx == 0 && ty == 0) ? 0.0f : 1.0f;
    float pxv = __ldg(px + (size_t)r * W + tx);
    float pyv = __ldg(py + (size_t)r * H + ty);
    float lpx  = fmaxf(__logf(pxv), -100.0f);
    float l1px = clog1m(pxv);
    float lpy  = fmaxf(__logf(pyv), -100.0f);
    float l1py = clog1m(pyv);
    float corr = (l1px - lpx) * invW + (l1py - lpy) * invH;
    g_mask[r] = m;
    g_corr[r] = m * corr;
}

// ---------------------------------------------------------------------------
// Main streaming reduction (vectorized float4 path)
// ---------------------------------------------------------------------------
template <int PR4>
__device__ __forceinline__ unsigned row_of(unsigned i, unsigned pr4) {
    return (PR4 > 0) ? (i / (unsigned)PR4) : (i / pr4);
}

__device__ __forceinline__ float sum4(float4 v) {
    float s = clog1m(v.x);
    s += clog1m(v.y);
    s += clog1m(v.z);
    s += clog1m(v.w);
    return s;
}

template <int PR4>
__device__ __forceinline__ float region_sum(const float4* __restrict__ p,
                                            unsigned n4, unsigned pr4,
                                            unsigned start, unsigned stride)
{
    float a0 = 0.f, a1 = 0.f, a2 = 0.f, a3 = 0.f;
    unsigned i = start;
    for (; i + 3u * stride < n4; i += 4u * stride) {
        unsigned i0 = i, i1 = i + stride, i2 = i + 2u * stride, i3 = i + 3u * stride;
        float4 v0 = __ldg(p + i0);
        float4 v1 = __ldg(p + i1);
        float4 v2 = __ldg(p + i2);
        float4 v3 = __ldg(p + i3);
        float m0 = g_mask[row_of<PR4>(i0, pr4)];
        float m1 = g_mask[row_of<PR4>(i1, pr4)];
        float m2 = g_mask[row_of<PR4>(i2, pr4)];
        float m3 = g_mask[row_of<PR4>(i3, pr4)];
        a0 += m0 * sum4(v0);
        a1 += m1 * sum4(v1);
        a2 += m2 * sum4(v2);
        a3 += m3 * sum4(v3);
    }
    for (; i < n4; i += stride) {
        float4 v = __ldg(p + i);
        a0 += g_mask[row_of<PR4>(i, pr4)] * sum4(v);
    }
    return (a0 + a1) + (a2 + a3);
}

__device__ __forceinline__ void block_reduce_store(float acc, float scale)
{
    __shared__ float sh[BLK / 32];
    unsigned tid = threadIdx.x;
    #pragma unroll
    for (int o = 16; o > 0; o >>= 1)
        acc += __shfl_down_sync(0xffffffffu, acc, o);
    if ((tid & 31u) == 0) sh[tid >> 5] = acc;
    __syncthreads();
    if (tid < (BLK / 32)) {
        float v = sh[tid];
        #pragma unroll
        for (int o = (BLK / 64); o > 0; o >>= 1)
            v += __shfl_down_sync(0xffu, v, o, BLK / 32);
        if (tid == 0) g_part[blockIdx.x] = v * scale;
    }
}

template <int PR4X, int PR4Y>
__global__ void __launch_bounds__(BLK) main_kernel(
    const float4* __restrict__ px4, const float4* __restrict__ py4,
    unsigned n4x, unsigned n4y, int blocksX, int blocksTotal,
    unsigned pr4x, unsigned pr4y, float invW, float invH)
{
    float acc, scale;
    unsigned tid = threadIdx.x;
    if ((int)blockIdx.x < blocksX) {
        unsigned stride = (unsigned)blocksX * (unsigned)BLK;
        acc = region_sum<PR4X>(px4, n4x, pr4x, blockIdx.x * (unsigned)BLK + tid, stride);
        scale = -invW;
    } else {
        unsigned bid = blockIdx.x - (unsigned)blocksX;
        unsigned nb = (unsigned)(blocksTotal - blocksX);
        unsigned stride = nb * (unsigned)BLK;
        acc = region_sum<PR4Y>(py4, n4y, pr4y, bid * (unsigned)BLK + tid, stride);
        scale = -invH;
    }
    block_reduce_store(acc, scale);
}

// Scalar fallback (W or H not divisible by 4) — correctness insurance only.
__global__ void __launch_bounds__(BLK) main_kernel_scalar(
    const float* __restrict__ px, const float* __restrict__ py,
    unsigned nx, unsigned ny, int blocksX, int blocksTotal,
    unsigned W, unsigned H, float invW, float invH)
{
    float acc = 0.f, scale;
    unsigned tid = threadIdx.x;
    if ((int)blockIdx.x < blocksX) {
        unsigned stride = (unsigned)blocksX * (unsigned)BLK;
        for (unsigned i = blockIdx.x * (unsigned)BLK + tid; i < nx; i += stride)
            acc += g_mask[i / W] * clog1m(__ldg(px + i));
        scale = -invW;
    } else {
        unsigned nb = (unsigned)(blocksTotal - blocksX);
        unsigned stride = nb * (unsigned)BLK;
        for (unsigned i = (blockIdx.x - (unsigned)blocksX) * (unsigned)BLK + tid; i < ny; i += stride)
            acc += g_mask[i / H] * clog1m(__ldg(py + i));
        scale = -invH;
    }
    block_reduce_store(acc, scale);
}

// ---------------------------------------------------------------------------
// Final: deterministic double-precision reduction of corrections + partials
// ---------------------------------------------------------------------------
__global__ void final_kernel(int rows, int nb, float* __restrict__ out)
{
    __shared__ double sh0[BLK], sh1[BLK], sh2[BLK];
    unsigned tid = threadIdx.x;

    float c0 = 0.f, c1 = 0.f, c2 = 0.f, c3 = 0.f;
    float m0 = 0.f, m1 = 0.f, m2 = 0.f, m3 = 0.f;
    int r = (int)tid;
    for (; r + 3 * BLK < rows; r += 4 * BLK) {
        c0 += g_corr[r];           m0 += g_mask[r];
        c1 += g_corr[r + BLK];     m1 += g_mask[r + BLK];
        c2 += g_corr[r + 2 * BLK]; m2 += g_mask[r + 2 * BLK];
        c3 += g_corr[r + 3 * BLK]; m3 += g_mask[r + 3 * BLK];
    }
    for (; r < rows; r += BLK) { c0 += g_corr[r]; m0 += g_mask[r]; }

    float p0 = 0.f;
    for (int b = (int)tid; b < nb; b += BLK) p0 += g_part[b];

    sh0[tid] = (double)((c0 + c1) + (c2 + c3));
    sh1[tid] = (double)((m0 + m1) + (m2 + m3));
    sh2[tid] = (double)p0;
    __syncthreads();
    for (int s = BLK / 2; s > 0; s >>= 1) {
        if ((int)tid < s) {
            sh0[tid] += sh0[tid + s];
            sh1[tid] += sh1[tid + s];
            sh2[tid] += sh2[tid + s];
        }
        __syncthreads();
    }
    if (tid == 0) {
        double denom = sh1[0] > 1.0 ? sh1[0] : 1.0;
        out[0] = (float)((sh0[0] + sh2[0]) / denom);
    }
}

// ---------------------------------------------------------------------------
// Launch
// ---------------------------------------------------------------------------
extern "C" void kernel_launch(void* const* d_in, const int* in_sizes, int n_in,
                              void* d_out, int out_size)
{
    const float*     px  = (const float*)d_in[0];
    const float*     py  = (const float*)d_in[1];
    const long long* tgt = (const long long*)d_in[2];
    float* out = (float*)d_out;

    int rows = in_sizes[2] / 2;
    int W = in_sizes[0] / rows;
    int H = in_sizes[1] / rows;
    float invW = 1.0f / (float)W;
    float invH = 1.0f / (float)H;

    setup_kernel<<<(rows + BLK - 1) / BLK, BLK>>>(px, py, tgt, rows, W, H, invW, invH);

    int blocksTotal = 1184;                  // ~8 blocks/SM worth of work, <= MAXPART
    unsigned long long nx = (unsigned long long)rows * (unsigned long long)W;
    unsigned long long ny = (unsigned long long)rows * (unsigned long long)H;
    int blocksX = (int)((nx * (unsigned long long)blocksTotal) / (nx + ny));
    if (blocksX < 1) blocksX = 1;
    if (blocksX > blocksTotal - 1) blocksX = blocksTotal - 1;

    if ((W % 4) == 0 && (H % 4) == 0) {
        unsigned n4x = (unsigned)(nx / 4ull);
        unsigned n4y = (unsigned)(ny / 4ull);
        unsigned pr4x = (unsigned)(W / 4);
        unsigned pr4y = (unsigned)(H / 4);
        if (pr4x == 480u && pr4y == 270u) {
            main_kernel<480, 270><<<blocksTotal, BLK>>>(
                (const float4*)px, (const float4*)py,
                n4x, n4y, blocksX, blocksTotal, pr4x, pr4y, invW, invH);
        } else {
            main_kernel<0, 0><<<blocksTotal, BLK>>>(
                (const float4*)px, (const float4*)py,
                n4x, n4y, blocksX, blocksTotal, pr4x, pr4y, invW, invH);
        }
    } else {
        main_kernel_scalar<<<blocksTotal, BLK>>>(
            px, py, (unsigned)nx, (unsigned)ny, blocksX, blocksTotal,
            (unsigned)W, (unsigned)H, invW, invH);
    }

    final_kernel<<<1, BLK>>>(rows, blocksTotal, out);
}